// round 15
// baseline (speedup 1.0000x reference)
#include <cuda_runtime.h>
#include <cuda_bf16.h>
#include <cstdint>

#define DIMC 512
#define HIDC 1024
#define NBATCH 16
#define NPIX 65536

// ---------------- scratch ----------------
__device__ __nv_bfloat16 g_h[(size_t)NPIX*DIMC];       // LN1 output
__device__ __nv_bfloat16 g_an[(size_t)NPIX*DIMC];      // row-normalized LN2 out (GEMM1 A)
__device__ __nv_bfloat16 g_hidden[(size_t)NPIX*HIDC];  // gelu(sim*si) (GEMM2 A)
__device__ __nv_bfloat16 g_win[(size_t)DIMC*HIDC];     // [K=512, N=1024] col-norm * scale_in
__device__ __nv_bfloat16 g_wout[(size_t)HIDC*DIMC];    // [K=1024, N=512] col-norm * scale_out*gamma
__device__ float g_gp[NBATCH*DIMC];
__device__ float g_rowsq[NPIX];

// ---------------- helpers ----------------
__device__ __forceinline__ float wredsum(float v) {
#pragma unroll
    for (int o = 16; o > 0; o >>= 1) v += __shfl_xor_sync(0xffffffffu, v, o);
    return v;
}
__device__ __forceinline__ void ld_bf8(const __nv_bfloat16* p, float* f) {
    uint4 u = __ldg((const uint4*)p);
    __nv_bfloat162 a = *(__nv_bfloat162*)&u.x;
    __nv_bfloat162 b = *(__nv_bfloat162*)&u.y;
    __nv_bfloat162 c = *(__nv_bfloat162*)&u.z;
    __nv_bfloat162 d = *(__nv_bfloat162*)&u.w;
    f[0] = __bfloat162float(a.x); f[1] = __bfloat162float(a.y);
    f[2] = __bfloat162float(b.x); f[3] = __bfloat162float(b.y);
    f[4] = __bfloat162float(c.x); f[5] = __bfloat162float(c.y);
    f[6] = __bfloat162float(d.x); f[7] = __bfloat162float(d.y);
}
__device__ __forceinline__ void st_bf8(__nv_bfloat16* p, const float* f) {
    __nv_bfloat162 a = __floats2bfloat162_rn(f[0], f[1]);
    __nv_bfloat162 b = __floats2bfloat162_rn(f[2], f[3]);
    __nv_bfloat162 c = __floats2bfloat162_rn(f[4], f[5]);
    __nv_bfloat162 d = __floats2bfloat162_rn(f[6], f[7]);
    uint4 u;
    u.x = *(uint32_t*)&a; u.y = *(uint32_t*)&b;
    u.z = *(uint32_t*)&c; u.w = *(uint32_t*)&d;
    *(uint4*)p = u;
}
__device__ __forceinline__ void st_bf4(__nv_bfloat16* p, float a, float b, float c, float d) {
    __nv_bfloat162 lo = __floats2bfloat162_rn(a, b);
    __nv_bfloat162 hi = __floats2bfloat162_rn(c, d);
    uint2 u; u.x = *(uint32_t*)&lo; u.y = *(uint32_t*)&hi;
    *(uint2*)p = u;
}
// fast GeLU: hardware tanh.approx; error ~3e-4 abs, damped 1e-3 into the residual
__device__ __forceinline__ float gelu_fast(float u) {
    float t;
    float z = 0.7978845608028654f * (u + 0.044715f * u * u * u);
    asm("tanh.approx.f32 %0, %1;" : "=f"(t) : "f"(z));
    return 0.5f * u * (1.0f + t);
}

// ---------------- K0: weight column-norm (coalesced, MLP-unrolled) ------------
__global__ void k_wnorm(const float* __restrict__ pin, const float* __restrict__ pout,
                        const float* __restrict__ s_in, const float* __restrict__ s_out,
                        const float* __restrict__ gamma) {
    int b = blockIdx.x, t = threadIdx.x;
    if (b < 8)
        for (int i = t; i < 1024; i += 256) g_gp[b*1024 + i] = 0.f;
    const float* src;
    __nv_bfloat16* dst;
    int K, N, j0;
    if (b < 16) { src = pin;  dst = g_win;  K = DIMC; N = HIDC; j0 = b * 64; }
    else        { src = pout; dst = g_wout; K = HIDC; N = DIMC; j0 = (b - 16) * 64; }
    int jl = t & 63, r0 = t >> 6;
    float ss = 0.f;
#pragma unroll 8
    for (int r = r0; r < K; r += 4) {
        float v = src[(size_t)r * N + j0 + jl];
        ss += v * v;
    }
    __shared__ float red[4][64];
    __shared__ float sinv[64];
    red[r0][jl] = ss;
    __syncthreads();
    if (t < 64) {
        float tot = red[0][t] + red[1][t] + red[2][t] + red[3][t];
        float inv = 1.f / fmaxf(sqrtf(tot), 1e-12f);
        int j = j0 + t;
        inv *= (b < 16) ? s_in[0] : (s_out[0] * gamma[j]);
        sinv[t] = inv;
    }
    __syncthreads();
    float inv = sinv[jl];
#pragma unroll 8
    for (int r = r0; r < K; r += 4)
        dst[(size_t)r * N + j0 + jl] = __float2bfloat16(src[(size_t)r * N + j0 + jl] * inv);
}

// ---------------- K1: LayerNorm1 -> g_h (bf16) + fused global-pool ------------
// grid 2048: (rowid, xhalf); warp = 4 px
__global__ __launch_bounds__(256, 2) void k_ln1(const float* __restrict__ x,
                                                const float* __restrict__ w,
                                                const float* __restrict__ bb) {
    __shared__ float s_w[DIMC], s_b[DIMC], sgp[DIMC];
    int rowid = blockIdx.x >> 1;
    int xh = (blockIdx.x & 1) * 32;
    int b = rowid >> 6;
    int t = threadIdx.x;
    for (int i = t; i < DIMC; i += 256) { s_w[i] = w[i]; s_b[i] = bb[i]; sgp[i] = 0.f; }
    __syncthreads();
    int warp = t >> 5, lane = t & 31, cb = lane * 4;
    float gacc[16];
#pragma unroll
    for (int i = 0; i < 16; i++) gacc[i] = 0.f;
#pragma unroll
    for (int px = 0; px < 4; ++px) {
        size_t p = (size_t)rowid * 64 + xh + warp * 4 + px;
        const float4* xp = (const float4*)(x + p * DIMC);
        float4 v[4];
        float s = 0.f, sq = 0.f;
#pragma unroll
        for (int i = 0; i < 4; i++) {
            v[i] = xp[lane + i*32];
            s  += v[i].x + v[i].y + v[i].z + v[i].w;
            sq += v[i].x*v[i].x + v[i].y*v[i].y + v[i].z*v[i].z + v[i].w*v[i].w;
        }
        s = wredsum(s); sq = wredsum(sq);
        float m = s * (1.f/512.f);
        float rstd = rsqrtf(sq * (1.f/512.f) - m*m + 1e-5f);
        __nv_bfloat16* hp = g_h + p * DIMC;
#pragma unroll
        for (int i = 0; i < 4; i++) {
            float4 w4 = *(const float4*)&s_w[cb + i*128];
            float4 b4 = *(const float4*)&s_b[cb + i*128];
            float h0 = (v[i].x - m)*rstd*w4.x + b4.x;
            float h1 = (v[i].y - m)*rstd*w4.y + b4.y;
            float h2 = (v[i].z - m)*rstd*w4.z + b4.z;
            float h3 = (v[i].w - m)*rstd*w4.w + b4.w;
            st_bf4(hp + cb + i*128, h0, h1, h2, h3);
            gacc[i*4+0] += h0; gacc[i*4+1] += h1; gacc[i*4+2] += h2; gacc[i*4+3] += h3;
        }
    }
#pragma unroll
    for (int i = 0; i < 4; i++)
#pragma unroll
        for (int q = 0; q < 4; q++)
            atomicAdd(&sgp[cb + i*128 + q], gacc[i*4+q]);
    __syncthreads();
    atomicAdd(&g_gp[b*DIMC + t], sgp[t]);
    atomicAdd(&g_gp[b*DIMC + t + 256], sgp[t + 256]);
}

// ---------------- K2: spatial + residual1 + LN2 + row L2 norm ----------------
// grid 2048: (rowid, xhalf); warp = 4 px; channel chunks of 8 (16B loads)
__global__ __launch_bounds__(256, 2) void k_spatial(const float* __restrict__ x,
                                                    const float* __restrict__ alpha,
                                                    const float* __restrict__ w2,
                                                    const float* __restrict__ b2,
                                                    const float* __restrict__ gamma,
                                                    float* __restrict__ out) {
    __shared__ float s_al[DIMC], s_gpc[DIMC], s_w[DIMC], s_b[DIMC], s_g[DIMC];
    int rowid = blockIdx.x >> 1;
    int xh = (blockIdx.x & 1) * 32;
    int b = rowid >> 6, y = rowid & 63;
    int t = threadIdx.x;
    for (int i = t; i < DIMC; i += 256) {
        float al = alpha[i];
        s_al[i] = al;
        s_gpc[i] = g_gp[b*DIMC + i] * (1.f - al) * (1.f/4096.f);
        s_w[i] = w2[i]; s_b[i] = b2[i]; s_g[i] = gamma[i];
    }
    __syncthreads();
    int warp = t >> 5, lane = t & 31;
#pragma unroll
    for (int px = 0; px < 4; ++px) {
        int xc = xh + warp * 4 + px;
        size_t p = (size_t)rowid * 64 + xc;
        const __nv_bfloat16* hC = g_h + p * DIMC;
        bool hasU = (y > 0), hasD = (y < 63), hasL = (xc > 0), hasR = (xc < 63);
        const float4* xp4 = (const float4*)(x + p * DIMC);
        float v[16], h2[16];
        float s = 0.f, sq = 0.f;
#pragma unroll
        for (int i = 0; i < 2; i++) {
            int off = lane * 8 + i * 256;
            float c8[8], u8[8], d8[8], l8[8], r8[8];
            ld_bf8(hC + off, c8);
            if (hasU) ld_bf8(hC - 64*DIMC + off, u8); else { for (int q=0;q<8;q++) u8[q]=0.f; }
            if (hasD) ld_bf8(hC + 64*DIMC + off, d8); else { for (int q=0;q<8;q++) d8[q]=0.f; }
            if (hasL) ld_bf8(hC - DIMC + off, l8);    else { for (int q=0;q<8;q++) l8[q]=0.f; }
            if (hasR) ld_bf8(hC + DIMC + off, r8);    else { for (int q=0;q<8;q++) r8[q]=0.f; }
            float4 xv0 = xp4[lane*2 + i*64];
            float4 xv1 = xp4[lane*2 + i*64 + 1];
            float xv[8] = {xv0.x, xv0.y, xv0.z, xv0.w, xv1.x, xv1.y, xv1.z, xv1.w};
#pragma unroll
            for (int q = 0; q < 8; q++) {
                float c = c8[q];
                float fe = fabsf(c-u8[q]) + fabsf(c-d8[q]) + fabsf(c-l8[q]) + fabsf(c-r8[q]);
                float sp = fe * s_al[off + q] + s_gpc[off + q];
                float vv = xv[q] + s_g[off + q] * sp;
                v[i*8 + q] = vv;
                s += vv;
                sq += vv * vv;
            }
        }
        s = wredsum(s); sq = wredsum(sq);
        float m = s * (1.f/512.f);
        float rstd = rsqrtf(sq * (1.f/512.f) - m*m + 1e-5f);
        float4* op = (float4*)(out + p * DIMC);
        float ss = 0.f;
#pragma unroll
        for (int i = 0; i < 2; i++) {
            int off = lane * 8 + i * 256;
#pragma unroll
            for (int q = 0; q < 8; q++) {
                float hh = (v[i*8 + q] - m) * rstd * s_w[off + q] + s_b[off + q];
                h2[i*8 + q] = hh;
                ss += hh * hh;
            }
            float4 o0 = make_float4(v[i*8+0], v[i*8+1], v[i*8+2], v[i*8+3]);
            float4 o1 = make_float4(v[i*8+4], v[i*8+5], v[i*8+6], v[i*8+7]);
            op[lane*2 + i*64]     = o0;
            op[lane*2 + i*64 + 1] = o1;
        }
        ss = wredsum(ss);
        float inv = 1.f / fmaxf(sqrtf(ss), 1e-12f);
        __nv_bfloat16* ap = g_an + p * DIMC;
#pragma unroll
        for (int i = 0; i < 2; i++) {
            int off = lane * 8 + i * 256;
            float hv[8];
#pragma unroll
            for (int q = 0; q < 8; q++) hv[q] = h2[i*8 + q] * inv;
            st_bf8(ap + off, hv);
        }
        if (lane == 0) g_rowsq[p] = 0.f;
    }
}

// == bf16 GEMM: CTA 128x128, BK=64, 8 warps (32x64 tiles), 2-stage, 3 CTAs/SM ==
#define NSTAGE 2
#define STGB 32768   // A 16KB + B 16KB per stage

__device__ __forceinline__ void cpa16(uint32_t s, const void* g) {
    asm volatile("cp.async.cg.shared.global [%0], [%1], 16;\n" :: "r"(s), "l"(g));
}
__device__ __forceinline__ uint32_t swzA(uint32_t o) { return o ^ ((o >> 3) & 0x70); } // 128B rows
__device__ __forceinline__ uint32_t swzB(uint32_t o) { return o ^ ((o >> 4) & 0x70); } // 256B rows

#define HMMA(d, a, b0v, b1v)                                               \
    asm volatile(                                                          \
        "mma.sync.aligned.m16n8k16.row.col.f32.bf16.bf16.f32 "             \
        "{%0,%1,%2,%3},{%4,%5,%6,%7},{%8,%9},{%0,%1,%2,%3};\n"             \
        : "+f"(d[0]), "+f"(d[1]), "+f"(d[2]), "+f"(d[3])                   \
        : "r"(a[0]), "r"(a[1]), "r"(a[2]), "r"(a[3]), "r"(b0v), "r"(b1v))

#define LDSM4(r0, r1, r2, r3, addr)                                        \
    asm volatile("ldmatrix.sync.aligned.m8n8.x4.shared.b16 {%0,%1,%2,%3},[%4];\n" \
                 : "=r"(r0), "=r"(r1), "=r"(r2), "=r"(r3) : "r"(addr))
#define LDSM4T(r0, r1, r2, r3, addr)                                       \
    asm volatile("ldmatrix.sync.aligned.m8n8.x4.trans.shared.b16 {%0,%1,%2,%3},[%4];\n" \
                 : "=r"(r0), "=r"(r1), "=r"(r2), "=r"(r3) : "r"(addr))

// EPI=1: A=g_an [M,512],  B=g_win  [512,1024] -> gelu -> g_hidden bf16 + rowsq
// EPI=2: A=g_hidden [M,1024], B=g_wout [1024,512] -> out += acc * rsqrt(rowsq)
template <int KDIM, int EPI>
__global__ __launch_bounds__(256, 3) void k_gemm(float* __restrict__ outp) {
    extern __shared__ __align__(1024) uint8_t sm[];
    const __nv_bfloat16* __restrict__ A  = (EPI == 1) ? g_an : g_hidden;
    const __nv_bfloat16* __restrict__ Bw = (EPI == 1) ? g_win : g_wout;
    const int NDIM = (EPI == 1) ? HIDC : DIMC;

    int tid = threadIdx.x, wid = tid >> 5, lane = tid & 31;
    int bm = blockIdx.y * 128, bn = blockIdx.x * 128;
    int wr = wid & 3, wc = wid >> 2;   // 4x2 warps of 32x64
    uint32_t smem_u = (uint32_t)__cvta_generic_to_shared(sm);

    const __nv_bfloat16* gA = A + (size_t)(bm + (tid >> 1)) * KDIM + (tid & 1) * 32;
    const __nv_bfloat16* gB = Bw + (size_t)(tid >> 2) * NDIM + bn + (tid & 3) * 32;
    uint32_t soA[4], soB[4];
#pragma unroll
    for (int c = 0; c < 4; c++) {
        soA[c] = swzA((uint32_t)(tid >> 1) * 128 + (tid & 1) * 64 + c * 16);
        soB[c] = 16384 + swzB((uint32_t)(tid >> 2) * 256 + (tid & 3) * 64 + c * 16);
    }

    float acc[2][8][4];
#pragma unroll
    for (int mi = 0; mi < 2; mi++)
#pragma unroll
        for (int ni = 0; ni < 8; ni++)
#pragma unroll
            for (int q = 0; q < 4; q++) acc[mi][ni][q] = 0.f;

    const int nkt = KDIM / 64;
#pragma unroll
    for (int pf = 0; pf < 2; pf++) {
        uint32_t base = smem_u + pf * STGB;
#pragma unroll
        for (int c = 0; c < 4; c++) {
            cpa16(base + soA[c], gA + pf * 64 + c * 8);
            cpa16(base + soB[c], gB + (size_t)(pf * 64) * NDIM + c * 8);
        }
        asm volatile("cp.async.commit_group;\n");
    }

#pragma unroll
    for (int kt = 0; kt < nkt; kt++) {
        if (kt + 1 < nkt) asm volatile("cp.async.wait_group 1;\n");
        else              asm volatile("cp.async.wait_group 0;\n");
        __syncthreads();
        uint32_t base = smem_u + (kt & 1) * STGB;
#pragma unroll
        for (int ks = 0; ks < 4; ks++) {
            int colb = ks * 32 + (lane >> 4) * 16;
            uint32_t a[2][4];
#pragma unroll
            for (int mi = 0; mi < 2; mi++) {
                uint32_t o = (uint32_t)(wr * 32 + mi * 16 + (lane & 15)) * 128 + colb;
                LDSM4(a[mi][0], a[mi][1], a[mi][2], a[mi][3], base + swzA(o));
            }
            int rrow = ks * 16 + ((lane >> 3) & 1) * 8 + (lane & 7);
#pragma unroll
            for (int nj = 0; nj < 4; nj++) {
                uint32_t r0, r1, r2, r3;
                uint32_t o = (uint32_t)rrow * 256 + (uint32_t)(wc * 64 + nj * 16 + (lane >> 4) * 8) * 2;
                LDSM4T(r0, r1, r2, r3, base + 16384 + swzB(o));
#pragma unroll
                for (int mi = 0; mi < 2; mi++) {
                    HMMA(acc[mi][2*nj],     a[mi], r0, r1);
                    HMMA(acc[mi][2*nj + 1], a[mi], r2, r3);
                }
            }
        }
        if (kt + 2 < nkt) {
            __syncthreads();   // everyone done reading stage (kt&1) before refill
#pragma unroll
            for (int c = 0; c < 4; c++) {
                cpa16(base + soA[c], gA + (kt + 2) * 64 + c * 8);
                cpa16(base + soB[c], gB + (size_t)((kt + 2) * 64) * NDIM + c * 8);
            }
            asm volatile("cp.async.commit_group;\n");
        }
    }

    if (EPI == 1) {
#pragma unroll
        for (int mi = 0; mi < 2; mi++) {
            int r0 = bm + wr * 32 + mi * 16 + (lane >> 2);
            int r1 = r0 + 8;
            float s0 = 0.f, s1 = 0.f;
#pragma unroll
            for (int ni = 0; ni < 8; ni++) {
                int c = bn + wc * 64 + ni * 8 + (lane & 3) * 2;
                float g0 = gelu_fast(acc[mi][ni][0]);
                float g1 = gelu_fast(acc[mi][ni][1]);
                float g2 = gelu_fast(acc[mi][ni][2]);
                float g3 = gelu_fast(acc[mi][ni][3]);
                *(__nv_bfloat162*)(g_hidden + (size_t)r0 * HIDC + c) = __floats2bfloat162_rn(g0, g1);
                *(__nv_bfloat162*)(g_hidden + (size_t)r1 * HIDC + c) = __floats2bfloat162_rn(g2, g3);
                s0 += g0*g0 + g1*g1;
                s1 += g2*g2 + g3*g3;
            }
            s0 += __shfl_xor_sync(0xffffffffu, s0, 1);
            s0 += __shfl_xor_sync(0xffffffffu, s0, 2);
            s1 += __shfl_xor_sync(0xffffffffu, s1, 1);
            s1 += __shfl_xor_sync(0xffffffffu, s1, 2);
            if ((lane & 3) == 0) {
                atomicAdd(&g_rowsq[r0], s0);
                atomicAdd(&g_rowsq[r1], s1);
            }
        }
    } else {
#pragma unroll
        for (int mi = 0; mi < 2; mi++) {
            int r0 = bm + wr * 32 + mi * 16 + (lane >> 2);
            int r1 = r0 + 8;
            float inv0 = 1.f / fmaxf(sqrtf(g_rowsq[r0]), 1e-12f);
            float inv1 = 1.f / fmaxf(sqrtf(g_rowsq[r1]), 1e-12f);
#pragma unroll
            for (int ni = 0; ni < 8; ni++) {
                int c = bn + wc * 64 + ni * 8 + (lane & 3) * 2;
                float2* p0 = (float2*)(outp + (size_t)r0 * DIMC + c);
                float2* p1 = (float2*)(outp + (size_t)r1 * DIMC + c);
                float2 o0 = *p0, o1 = *p1;
                o0.x += acc[mi][ni][0] * inv0;
                o0.y += acc[mi][ni][1] * inv0;
                o1.x += acc[mi][ni][2] * inv1;
                o1.y += acc[mi][ni][3] * inv1;
                *p0 = o0; *p1 = o1;
            }
        }
    }
}

// ---------------- launch ----------------
extern "C" void kernel_launch(void* const* d_in, const int* in_sizes, int n_in,
                              void* d_out, int out_size) {
    const float* x     = (const float*)d_in[0];
    const float* n1w   = (const float*)d_in[1];
    const float* n1b   = (const float*)d_in[2];
    const float* alpha = (const float*)d_in[3];
    const float* n2w   = (const float*)d_in[4];
    const float* n2b   = (const float*)d_in[5];
    const float* pin   = (const float*)d_in[6];
    const float* pout  = (const float*)d_in[7];
    const float* s_in  = (const float*)d_in[8];
    const float* s_out = (const float*)d_in[9];
    const float* gamma = (const float*)d_in[10];
    float* out = (float*)d_out;

    cudaFuncSetAttribute(k_gemm<512, 1>,  cudaFuncAttributeMaxDynamicSharedMemorySize, NSTAGE*STGB);
    cudaFuncSetAttribute(k_gemm<1024, 2>, cudaFuncAttributeMaxDynamicSharedMemorySize, NSTAGE*STGB);

    // fork: wnorm runs concurrently with the ln1 -> spatial chain
    static cudaStream_t s2 = nullptr;
    static cudaEvent_t evFork = nullptr, evJoin = nullptr;
    if (s2 == nullptr) {
        cudaStreamCreateWithFlags(&s2, cudaStreamNonBlocking);
        cudaEventCreateWithFlags(&evFork, cudaEventDisableTiming);
        cudaEventCreateWithFlags(&evJoin, cudaEventDisableTiming);
    }

    cudaEventRecord(evFork, 0);
    cudaStreamWaitEvent(s2, evFork, 0);
    k_wnorm<<<24, 256, 0, s2>>>(pin, pout, s_in, s_out, gamma);
    cudaEventRecord(evJoin, s2);

    k_ln1<<<NBATCH * 128, 256>>>(x, n1w, n1b);
    k_spatial<<<NBATCH * 128, 256>>>(x, alpha, n2w, n2b, gamma, out);

    cudaStreamWaitEvent(0, evJoin, 0);
    k_gemm<512, 1><<<dim3(HIDC / 128, NPIX / 128), 256, NSTAGE*STGB>>>(nullptr);
    k_gemm<1024, 2><<<dim3(DIMC / 128, NPIX / 128), 256, NSTAGE*STGB>>>(out);
}

// round 16
// speedup vs baseline: 1.7795x; 1.7795x over previous
#include <cuda_runtime.h>
#include <cuda_bf16.h>
#include <cstdint>

#define DIMC 512
#define HIDC 1024
#define NBATCH 16
#define NPIX 65536

// ---------------- scratch ----------------
__device__ __nv_bfloat16 g_h[(size_t)NPIX*DIMC];       // LN1 output
__device__ __nv_bfloat16 g_an[(size_t)NPIX*DIMC];      // row-normalized LN2 out (GEMM1 A)
__device__ __nv_bfloat16 g_hidden[(size_t)NPIX*HIDC];  // gelu(sim*si) (GEMM2 A)
__device__ __nv_bfloat16 g_win[(size_t)DIMC*HIDC];     // [K=512, N=1024] col-norm * scale_in
__device__ __nv_bfloat16 g_wout[(size_t)HIDC*DIMC];    // [K=1024, N=512] col-norm * scale_out*gamma
__device__ float g_gp[NBATCH*DIMC];
__device__ float g_rowsq[NPIX];

// ---------------- helpers ----------------
__device__ __forceinline__ float wredsum(float v) {
#pragma unroll
    for (int o = 16; o > 0; o >>= 1) v += __shfl_xor_sync(0xffffffffu, v, o);
    return v;
}
__device__ __forceinline__ void ld_bf8(const __nv_bfloat16* p, float* f) {
    uint4 u = __ldg((const uint4*)p);
    __nv_bfloat162 a = *(__nv_bfloat162*)&u.x;
    __nv_bfloat162 b = *(__nv_bfloat162*)&u.y;
    __nv_bfloat162 c = *(__nv_bfloat162*)&u.z;
    __nv_bfloat162 d = *(__nv_bfloat162*)&u.w;
    f[0] = __bfloat162float(a.x); f[1] = __bfloat162float(a.y);
    f[2] = __bfloat162float(b.x); f[3] = __bfloat162float(b.y);
    f[4] = __bfloat162float(c.x); f[5] = __bfloat162float(c.y);
    f[6] = __bfloat162float(d.x); f[7] = __bfloat162float(d.y);
}
__device__ __forceinline__ void st_bf8(__nv_bfloat16* p, const float* f) {
    __nv_bfloat162 a = __floats2bfloat162_rn(f[0], f[1]);
    __nv_bfloat162 b = __floats2bfloat162_rn(f[2], f[3]);
    __nv_bfloat162 c = __floats2bfloat162_rn(f[4], f[5]);
    __nv_bfloat162 d = __floats2bfloat162_rn(f[6], f[7]);
    uint4 u;
    u.x = *(uint32_t*)&a; u.y = *(uint32_t*)&b;
    u.z = *(uint32_t*)&c; u.w = *(uint32_t*)&d;
    *(uint4*)p = u;
}
__device__ __forceinline__ void st_bf4(__nv_bfloat16* p, float a, float b, float c, float d) {
    __nv_bfloat162 lo = __floats2bfloat162_rn(a, b);
    __nv_bfloat162 hi = __floats2bfloat162_rn(c, d);
    uint2 u; u.x = *(uint32_t*)&lo; u.y = *(uint32_t*)&hi;
    *(uint2*)p = u;
}
// fast GeLU: hardware tanh.approx; error ~3e-4 abs, damped 1e-3 into the residual
__device__ __forceinline__ float gelu_fast(float u) {
    float t;
    float z = 0.7978845608028654f * (u + 0.044715f * u * u * u);
    asm("tanh.approx.f32 %0, %1;" : "=f"(t) : "f"(z));
    return 0.5f * u * (1.0f + t);
}

// ---------------- K0: weight column-norm (coalesced, MLP-unrolled) ------------
__global__ void k_wnorm(const float* __restrict__ pin, const float* __restrict__ pout,
                        const float* __restrict__ s_in, const float* __restrict__ s_out,
                        const float* __restrict__ gamma) {
    int b = blockIdx.x, t = threadIdx.x;
    if (b < 8)
        for (int i = t; i < 1024; i += 256) g_gp[b*1024 + i] = 0.f;
    const float* src;
    __nv_bfloat16* dst;
    int K, N, j0;
    if (b < 16) { src = pin;  dst = g_win;  K = DIMC; N = HIDC; j0 = b * 64; }
    else        { src = pout; dst = g_wout; K = HIDC; N = DIMC; j0 = (b - 16) * 64; }
    int jl = t & 63, r0 = t >> 6;
    float ss = 0.f;
#pragma unroll 8
    for (int r = r0; r < K; r += 4) {
        float v = src[(size_t)r * N + j0 + jl];
        ss += v * v;
    }
    __shared__ float red[4][64];
    __shared__ float sinv[64];
    red[r0][jl] = ss;
    __syncthreads();
    if (t < 64) {
        float tot = red[0][t] + red[1][t] + red[2][t] + red[3][t];
        float inv = 1.f / fmaxf(sqrtf(tot), 1e-12f);
        int j = j0 + t;
        inv *= (b < 16) ? s_in[0] : (s_out[0] * gamma[j]);
        sinv[t] = inv;
    }
    __syncthreads();
    float inv = sinv[jl];
#pragma unroll 8
    for (int r = r0; r < K; r += 4)
        dst[(size_t)r * N + j0 + jl] = __float2bfloat16(src[(size_t)r * N + j0 + jl] * inv);
}

// ---------------- K1: LayerNorm1 -> g_h (bf16) + fused global-pool ------------
// grid 2048: (rowid, xhalf); warp = 4 px
__global__ __launch_bounds__(256, 2) void k_ln1(const float* __restrict__ x,
                                                const float* __restrict__ w,
                                                const float* __restrict__ bb) {
    __shared__ float s_w[DIMC], s_b[DIMC], sgp[DIMC];
    int rowid = blockIdx.x >> 1;
    int xh = (blockIdx.x & 1) * 32;
    int b = rowid >> 6;
    int t = threadIdx.x;
    for (int i = t; i < DIMC; i += 256) { s_w[i] = w[i]; s_b[i] = bb[i]; sgp[i] = 0.f; }
    __syncthreads();
    int warp = t >> 5, lane = t & 31, cb = lane * 4;
    float gacc[16];
#pragma unroll
    for (int i = 0; i < 16; i++) gacc[i] = 0.f;
#pragma unroll
    for (int px = 0; px < 4; ++px) {
        size_t p = (size_t)rowid * 64 + xh + warp * 4 + px;
        const float4* xp = (const float4*)(x + p * DIMC);
        float4 v[4];
        float s = 0.f, sq = 0.f;
#pragma unroll
        for (int i = 0; i < 4; i++) {
            v[i] = xp[lane + i*32];
            s  += v[i].x + v[i].y + v[i].z + v[i].w;
            sq += v[i].x*v[i].x + v[i].y*v[i].y + v[i].z*v[i].z + v[i].w*v[i].w;
        }
        s = wredsum(s); sq = wredsum(sq);
        float m = s * (1.f/512.f);
        float rstd = rsqrtf(sq * (1.f/512.f) - m*m + 1e-5f);
        __nv_bfloat16* hp = g_h + p * DIMC;
#pragma unroll
        for (int i = 0; i < 4; i++) {
            float4 w4 = *(const float4*)&s_w[cb + i*128];
            float4 b4 = *(const float4*)&s_b[cb + i*128];
            float h0 = (v[i].x - m)*rstd*w4.x + b4.x;
            float h1 = (v[i].y - m)*rstd*w4.y + b4.y;
            float h2 = (v[i].z - m)*rstd*w4.z + b4.z;
            float h3 = (v[i].w - m)*rstd*w4.w + b4.w;
            st_bf4(hp + cb + i*128, h0, h1, h2, h3);
            gacc[i*4+0] += h0; gacc[i*4+1] += h1; gacc[i*4+2] += h2; gacc[i*4+3] += h3;
        }
    }
#pragma unroll
    for (int i = 0; i < 4; i++)
#pragma unroll
        for (int q = 0; q < 4; q++)
            atomicAdd(&sgp[cb + i*128 + q], gacc[i*4+q]);
    __syncthreads();
    atomicAdd(&g_gp[b*DIMC + t], sgp[t]);
    atomicAdd(&g_gp[b*DIMC + t + 256], sgp[t + 256]);
}

// ---------------- K2: spatial + residual1 + LN2 + row L2 norm ----------------
// grid 2048: (rowid, xhalf); warp = 4 px; channel chunks of 8 (16B loads)
__global__ __launch_bounds__(256, 2) void k_spatial(const float* __restrict__ x,
                                                    const float* __restrict__ alpha,
                                                    const float* __restrict__ w2,
                                                    const float* __restrict__ b2,
                                                    const float* __restrict__ gamma,
                                                    float* __restrict__ out) {
    __shared__ float s_al[DIMC], s_gpc[DIMC], s_w[DIMC], s_b[DIMC], s_g[DIMC];
    int rowid = blockIdx.x >> 1;
    int xh = (blockIdx.x & 1) * 32;
    int b = rowid >> 6, y = rowid & 63;
    int t = threadIdx.x;
    for (int i = t; i < DIMC; i += 256) {
        float al = alpha[i];
        s_al[i] = al;
        s_gpc[i] = g_gp[b*DIMC + i] * (1.f - al) * (1.f/4096.f);
        s_w[i] = w2[i]; s_b[i] = b2[i]; s_g[i] = gamma[i];
    }
    __syncthreads();
    int warp = t >> 5, lane = t & 31;
#pragma unroll
    for (int px = 0; px < 4; ++px) {
        int xc = xh + warp * 4 + px;
        size_t p = (size_t)rowid * 64 + xc;
        const __nv_bfloat16* hC = g_h + p * DIMC;
        bool hasU = (y > 0), hasD = (y < 63), hasL = (xc > 0), hasR = (xc < 63);
        const float4* xp4 = (const float4*)(x + p * DIMC);
        float v[16], h2[16];
        float s = 0.f, sq = 0.f;
#pragma unroll
        for (int i = 0; i < 2; i++) {
            int off = lane * 8 + i * 256;
            float c8[8], u8[8], d8[8], l8[8], r8[8];
            ld_bf8(hC + off, c8);
            if (hasU) ld_bf8(hC - 64*DIMC + off, u8); else { for (int q=0;q<8;q++) u8[q]=0.f; }
            if (hasD) ld_bf8(hC + 64*DIMC + off, d8); else { for (int q=0;q<8;q++) d8[q]=0.f; }
            if (hasL) ld_bf8(hC - DIMC + off, l8);    else { for (int q=0;q<8;q++) l8[q]=0.f; }
            if (hasR) ld_bf8(hC + DIMC + off, r8);    else { for (int q=0;q<8;q++) r8[q]=0.f; }
            float4 xv0 = xp4[lane*2 + i*64];
            float4 xv1 = xp4[lane*2 + i*64 + 1];
            float xv[8] = {xv0.x, xv0.y, xv0.z, xv0.w, xv1.x, xv1.y, xv1.z, xv1.w};
#pragma unroll
            for (int q = 0; q < 8; q++) {
                float c = c8[q];
                float fe = fabsf(c-u8[q]) + fabsf(c-d8[q]) + fabsf(c-l8[q]) + fabsf(c-r8[q]);
                float sp = fe * s_al[off + q] + s_gpc[off + q];
                float vv = xv[q] + s_g[off + q] * sp;
                v[i*8 + q] = vv;
                s += vv;
                sq += vv * vv;
            }
        }
        s = wredsum(s); sq = wredsum(sq);
        float m = s * (1.f/512.f);
        float rstd = rsqrtf(sq * (1.f/512.f) - m*m + 1e-5f);
        float4* op = (float4*)(out + p * DIMC);
        float ss = 0.f;
#pragma unroll
        for (int i = 0; i < 2; i++) {
            int off = lane * 8 + i * 256;
#pragma unroll
            for (int q = 0; q < 8; q++) {
                float hh = (v[i*8 + q] - m) * rstd * s_w[off + q] + s_b[off + q];
                h2[i*8 + q] = hh;
                ss += hh * hh;
            }
            float4 o0 = make_float4(v[i*8+0], v[i*8+1], v[i*8+2], v[i*8+3]);
            float4 o1 = make_float4(v[i*8+4], v[i*8+5], v[i*8+6], v[i*8+7]);
            op[lane*2 + i*64]     = o0;
            op[lane*2 + i*64 + 1] = o1;
        }
        ss = wredsum(ss);
        float inv = 1.f / fmaxf(sqrtf(ss), 1e-12f);
        __nv_bfloat16* ap = g_an + p * DIMC;
#pragma unroll
        for (int i = 0; i < 2; i++) {
            int off = lane * 8 + i * 256;
            float hv[8];
#pragma unroll
            for (int q = 0; q < 8; q++) hv[q] = h2[i*8 + q] * inv;
            st_bf8(ap + off, hv);
        }
        if (lane == 0) g_rowsq[p] = 0.f;
    }
}

// ======== bf16 GEMM: CTA 128x128, BK=64, 8 warps (32x64 tiles), 3-stage ======
#define NSTAGE 3
#define STGB 32768   // A 16KB + B 16KB per stage

__device__ __forceinline__ void cpa16(uint32_t s, const void* g) {
    asm volatile("cp.async.cg.shared.global [%0], [%1], 16;\n" :: "r"(s), "l"(g));
}
__device__ __forceinline__ uint32_t swzA(uint32_t o) { return o ^ ((o >> 3) & 0x70); } // 128B rows
__device__ __forceinline__ uint32_t swzB(uint32_t o) { return o ^ ((o >> 4) & 0x70); } // 256B rows

#define HMMA(d, a, b0v, b1v)                                               \
    asm volatile(                                                          \
        "mma.sync.aligned.m16n8k16.row.col.f32.bf16.bf16.f32 "             \
        "{%0,%1,%2,%3},{%4,%5,%6,%7},{%8,%9},{%0,%1,%2,%3};\n"             \
        : "+f"(d[0]), "+f"(d[1]), "+f"(d[2]), "+f"(d[3])                   \
        : "r"(a[0]), "r"(a[1]), "r"(a[2]), "r"(a[3]), "r"(b0v), "r"(b1v))

#define LDSM4(r0, r1, r2, r3, addr)                                        \
    asm volatile("ldmatrix.sync.aligned.m8n8.x4.shared.b16 {%0,%1,%2,%3},[%4];\n" \
                 : "=r"(r0), "=r"(r1), "=r"(r2), "=r"(r3) : "r"(addr))
#define LDSM4T(r0, r1, r2, r3, addr)                                       \
    asm volatile("ldmatrix.sync.aligned.m8n8.x4.trans.shared.b16 {%0,%1,%2,%3},[%4];\n" \
                 : "=r"(r0), "=r"(r1), "=r"(r2), "=r"(r3) : "r"(addr))

// EPI=1: A=g_an [M,512],  B=g_win  [512,1024] -> gelu -> g_hidden bf16 + rowsq
// EPI=2: A=g_hidden [M,1024], B=g_wout [1024,512] -> out += acc * rsqrt(rowsq)
template <int KDIM, int EPI>
__global__ __launch_bounds__(256, 2) void k_gemm(float* __restrict__ outp) {
    extern __shared__ __align__(1024) uint8_t sm[];
    const __nv_bfloat16* __restrict__ A  = (EPI == 1) ? g_an : g_hidden;
    const __nv_bfloat16* __restrict__ Bw = (EPI == 1) ? g_win : g_wout;
    const int NDIM = (EPI == 1) ? HIDC : DIMC;

    int tid = threadIdx.x, wid = tid >> 5, lane = tid & 31;
    int bm = blockIdx.y * 128, bn = blockIdx.x * 128;
    int wr = wid & 3, wc = wid >> 2;   // 4x2 warps of 32x64
    uint32_t smem_u = (uint32_t)__cvta_generic_to_shared(sm);

    const __nv_bfloat16* gA = A + (size_t)(bm + (tid >> 1)) * KDIM + (tid & 1) * 32;
    const __nv_bfloat16* gB = Bw + (size_t)(tid >> 2) * NDIM + bn + (tid & 3) * 32;
    uint32_t soA[4], soB[4];
#pragma unroll
    for (int c = 0; c < 4; c++) {
        soA[c] = swzA((uint32_t)(tid >> 1) * 128 + (tid & 1) * 64 + c * 16);
        soB[c] = 16384 + swzB((uint32_t)(tid >> 2) * 256 + (tid & 3) * 64 + c * 16);
    }

    float acc[2][8][4];
#pragma unroll
    for (int mi = 0; mi < 2; mi++)
#pragma unroll
        for (int ni = 0; ni < 8; ni++)
#pragma unroll
            for (int q = 0; q < 4; q++) acc[mi][ni][q] = 0.f;

    const int nkt = KDIM / 64;
#pragma unroll
    for (int pf = 0; pf < 2; pf++) {
        uint32_t base = smem_u + pf * STGB;
#pragma unroll
        for (int c = 0; c < 4; c++) {
            cpa16(base + soA[c], gA + pf * 64 + c * 8);
            cpa16(base + soB[c], gB + (size_t)(pf * 64) * NDIM + c * 8);
        }
        asm volatile("cp.async.commit_group;\n");
    }

#pragma unroll
    for (int kt = 0; kt < nkt; kt++) {
        if (kt == nkt - 1) asm volatile("cp.async.wait_group 0;\n");
        else               asm volatile("cp.async.wait_group 1;\n");
        __syncthreads();
        // top sync also covers the stage the prefetch below overwrites
        if (kt + 2 < nkt) {
            uint32_t base = smem_u + ((kt + 2) % NSTAGE) * STGB;
#pragma unroll
            for (int c = 0; c < 4; c++) {
                cpa16(base + soA[c], gA + (kt + 2) * 64 + c * 8);
                cpa16(base + soB[c], gB + (size_t)((kt + 2) * 64) * NDIM + c * 8);
            }
            asm volatile("cp.async.commit_group;\n");
        }
        uint32_t base = smem_u + (kt % NSTAGE) * STGB;
#pragma unroll
        for (int ks = 0; ks < 4; ks++) {
            int colb = ks * 32 + (lane >> 4) * 16;
            uint32_t a[2][4];
#pragma unroll
            for (int mi = 0; mi < 2; mi++) {
                uint32_t o = (uint32_t)(wr * 32 + mi * 16 + (lane & 15)) * 128 + colb;
                LDSM4(a[mi][0], a[mi][1], a[mi][2], a[mi][3], base + swzA(o));
            }
            int rrow = ks * 16 + ((lane >> 3) & 1) * 8 + (lane & 7);
#pragma unroll
            for (int nj = 0; nj < 4; nj++) {
                uint32_t r0, r1, r2, r3;
                uint32_t o = (uint32_t)rrow * 256 + (uint32_t)(wc * 64 + nj * 16 + (lane >> 4) * 8) * 2;
                LDSM4T(r0, r1, r2, r3, base + 16384 + swzB(o));
#pragma unroll
                for (int mi = 0; mi < 2; mi++) {
                    HMMA(acc[mi][2*nj],     a[mi], r0, r1);
                    HMMA(acc[mi][2*nj + 1], a[mi], r2, r3);
                }
            }
        }
    }

    if (EPI == 1) {
#pragma unroll
        for (int mi = 0; mi < 2; mi++) {
            int r0 = bm + wr * 32 + mi * 16 + (lane >> 2);
            int r1 = r0 + 8;
            float s0 = 0.f, s1 = 0.f;
#pragma unroll
            for (int ni = 0; ni < 8; ni++) {
                int c = bn + wc * 64 + ni * 8 + (lane & 3) * 2;
                float g0 = gelu_fast(acc[mi][ni][0]);
                float g1 = gelu_fast(acc[mi][ni][1]);
                float g2 = gelu_fast(acc[mi][ni][2]);
                float g3 = gelu_fast(acc[mi][ni][3]);
                *(__nv_bfloat162*)(g_hidden + (size_t)r0 * HIDC + c) = __floats2bfloat162_rn(g0, g1);
                *(__nv_bfloat162*)(g_hidden + (size_t)r1 * HIDC + c) = __floats2bfloat162_rn(g2, g3);
                s0 += g0*g0 + g1*g1;
                s1 += g2*g2 + g3*g3;
            }
            s0 += __shfl_xor_sync(0xffffffffu, s0, 1);
            s0 += __shfl_xor_sync(0xffffffffu, s0, 2);
            s1 += __shfl_xor_sync(0xffffffffu, s1, 1);
            s1 += __shfl_xor_sync(0xffffffffu, s1, 2);
            if ((lane & 3) == 0) {
                atomicAdd(&g_rowsq[r0], s0);
                atomicAdd(&g_rowsq[r1], s1);
            }
        }
    } else {
        // hoist rowsq loads: start both dependent loads before the math
        int rr0 = bm + wr * 32 + (lane >> 2);
        float rs0 = g_rowsq[rr0];
        float rs1 = g_rowsq[rr0 + 8];
        float rs2 = g_rowsq[rr0 + 16];
        float rs3 = g_rowsq[rr0 + 24];
        float iv[4];
        iv[0] = 1.f / fmaxf(sqrtf(rs0), 1e-12f);
        iv[1] = 1.f / fmaxf(sqrtf(rs1), 1e-12f);
        iv[2] = 1.f / fmaxf(sqrtf(rs2), 1e-12f);
        iv[3] = 1.f / fmaxf(sqrtf(rs3), 1e-12f);
#pragma unroll
        for (int mi = 0; mi < 2; mi++) {
            int r0 = bm + wr * 32 + mi * 16 + (lane >> 2);
            int r1 = r0 + 8;
            float inv0 = iv[mi*2];
            float inv1 = iv[mi*2 + 1];
#pragma unroll
            for (int ni = 0; ni < 8; ni++) {
                int c = bn + wc * 64 + ni * 8 + (lane & 3) * 2;
                float2* p0 = (float2*)(outp + (size_t)r0 * DIMC + c);
                float2* p1 = (float2*)(outp + (size_t)r1 * DIMC + c);
                float2 o0 = *p0, o1 = *p1;
                o0.x += acc[mi][ni][0] * inv0;
                o0.y += acc[mi][ni][1] * inv0;
                o1.x += acc[mi][ni][2] * inv1;
                o1.y += acc[mi][ni][3] * inv1;
                *p0 = o0; *p1 = o1;
            }
        }
    }
}

// ---------------- launch ----------------
extern "C" void kernel_launch(void* const* d_in, const int* in_sizes, int n_in,
                              void* d_out, int out_size) {
    const float* x     = (const float*)d_in[0];
    const float* n1w   = (const float*)d_in[1];
    const float* n1b   = (const float*)d_in[2];
    const float* alpha = (const float*)d_in[3];
    const float* n2w   = (const float*)d_in[4];
    const float* n2b   = (const float*)d_in[5];
    const float* pin   = (const float*)d_in[6];
    const float* pout  = (const float*)d_in[7];
    const float* s_in  = (const float*)d_in[8];
    const float* s_out = (const float*)d_in[9];
    const float* gamma = (const float*)d_in[10];
    float* out = (float*)d_out;

    cudaFuncSetAttribute(k_gemm<512, 1>,  cudaFuncAttributeMaxDynamicSharedMemorySize, NSTAGE*STGB);
    cudaFuncSetAttribute(k_gemm<1024, 2>, cudaFuncAttributeMaxDynamicSharedMemorySize, NSTAGE*STGB);

    // fork: wnorm runs concurrently with the ln1 -> spatial chain
    static cudaStream_t s2 = nullptr;
    static cudaEvent_t evFork = nullptr, evJoin = nullptr;
    if (s2 == nullptr) {
        cudaStreamCreateWithFlags(&s2, cudaStreamNonBlocking);
        cudaEventCreateWithFlags(&evFork, cudaEventDisableTiming);
        cudaEventCreateWithFlags(&evJoin, cudaEventDisableTiming);
    }

    cudaEventRecord(evFork, 0);
    cudaStreamWaitEvent(s2, evFork, 0);
    k_wnorm<<<24, 256, 0, s2>>>(pin, pout, s_in, s_out, gamma);
    cudaEventRecord(evJoin, s2);

    k_ln1<<<NBATCH * 128, 256>>>(x, n1w, n1b);
    k_spatial<<<NBATCH * 128, 256>>>(x, alpha, n2w, n2b, gamma, out);

    cudaStreamWaitEvent(0, evJoin, 0);
    k_gemm<512, 1><<<dim3(HIDC / 128, NPIX / 128), 256, NSTAGE*STGB>>>(nullptr);
    k_gemm<1024, 2><<<dim3(DIMC / 128, NPIX / 128), 256, NSTAGE*STGB>>>(out);
}